// round 15
// baseline (speedup 1.0000x reference)
#include <cuda_runtime.h>
#include <cuda_fp16.h>
#include <cstdint>

// ---------------------------------------------------------------------------
// Fused hypercomplex (8-component Cayley-Dickson) ConvTranspose2d
//   x[8,512,64,64] fp32, W[8,64,32,4,4], b[8,32] -> out[8,256,128,128]
//   4 output parity classes, each: C[256, 32768] = A[256, 2048] * B[2048, 32768]
// HMMA m16n8k16, fp16 operands, fp32 accumulation.
// Round 15: R14 frozen (best: A ping-pong, hoisted dual LDSM, 3-stage
//           cp.async, 2 CTAs/SM) + vectorized x_transpose (float4/uint4)
//           + A staged with cp.async.ca (L1 hit for the co-resident CTA).
// ---------------------------------------------------------------------------

#define CIN   512
#define COUT  256
#define HIN   64
#define HOUT  128
#define GK    2048
#define BM    128
#define BN    128
#define BK    64
#define KT    (GK / BK)       // 32 k-tiles
#define THREADS 256
#define STAGES 3

#define A_TILE_BYTES 16384                    // 4 ks x 8 m16 x 32 lane x 16 B
#define B_TILE_BYTES 16384                    // 128 rows x 128 B
#define STAGE_BYTES  (A_TILE_BYTES + B_TILE_BYTES)
#define SMEM_BYTES   (STAGES * STAGE_BYTES)   // 96 KB

// Padded transposed x: [img][ih+1:0..65][iw+1:0..65][ci] fp16, zero borders
#define XT_HW 66
__device__ __align__(1024) __half g_Xt[8 * XT_HW * XT_HW * CIN];  // ~34 MB
// A in m16n8k16 fragment-major order:
// [cls 4][m16 16][k16 128][lane 32][reg 4] as uint32 (reg = pair of halves)
__device__ __align__(1024) uint32_t g_Af[4 * 16 * 128 * 32 * 4];  // 4 MB
__device__ __align__(16)   float  g_bias[COUT];

// Cayley-Dickson component table for n=8 (validated in round 1)
__device__ const int comp_tab[8][8] = {
    { 0,-1,-2,-1,-4,-3,-2,-3},
    { 1, 0,-3,-2,-5,-4,-1,-2},
    { 2, 1, 0,-1,-6,-5,-4,-3},
    { 3, 2, 1, 0,-7,-6,-5,-4},
    { 4, 3, 2, 3, 0,-1,-2,-1},
    { 5, 4, 1, 2, 1, 0,-3,-2},
    { 6, 5, 4, 3, 2, 1, 0,-1},
    { 7, 6, 5, 4, 3, 2, 1, 0},
};

// ------------------------------- PTX helpers -------------------------------
__device__ __forceinline__ uint32_t smem_u32(const void* p) {
    return (uint32_t)__cvta_generic_to_shared(p);
}

#define SWZ128(o) ((o) ^ (((o) >> 3) & 0x70))

#define CP_ASYNC16(smem_addr, gptr) \
    asm volatile("cp.async.cg.shared.global [%0], [%1], 16;" \
                 :: "r"(smem_addr), "l"(gptr) : "memory")
// .ca variant: keeps the line in L1 (A chunks are shared by the co-resident
// CTA, which then hits L1 instead of L2).
#define CP_ASYNC16_CA(smem_addr, gptr) \
    asm volatile("cp.async.ca.shared.global [%0], [%1], 16;" \
                 :: "r"(smem_addr), "l"(gptr) : "memory")
#define CP_COMMIT() asm volatile("cp.async.commit_group;" ::: "memory")
#define CP_WAIT0()  asm volatile("cp.async.wait_group 0;" ::: "memory")
#define CP_WAIT1()  asm volatile("cp.async.wait_group 1;" ::: "memory")

#define LDSM_X4(r0, r1, r2, r3, addr) \
    asm volatile("ldmatrix.sync.aligned.m8n8.x4.shared.b16 {%0,%1,%2,%3}, [%4];" \
                 : "=r"(r0), "=r"(r1), "=r"(r2), "=r"(r3) : "r"(addr))

#define LDS128(v, addr) \
    asm volatile("ld.shared.v4.u32 {%0,%1,%2,%3}, [%4];" \
                 : "=r"((v).x), "=r"((v).y), "=r"((v).z), "=r"((v).w) \
                 : "r"(addr))

#define MMA16816(d, a0, a1, a2, a3, b0, b1) \
    asm volatile("mma.sync.aligned.m16n8k16.row.col.f32.f16.f16.f32 " \
                 "{%0,%1,%2,%3}, {%4,%5,%6,%7}, {%8,%9}, {%0,%1,%2,%3};" \
                 : "+f"((d)[0]), "+f"((d)[1]), "+f"((d)[2]), "+f"((d)[3]) \
                 : "r"(a0), "r"(a1), "r"(a2), "r"(a3), "r"(b0), "r"(b1))

// ------------------------------- prep kernels ------------------------------

// Fused weight value for (cls, co, k) where k = tap*512 + ci
__device__ __forceinline__ float fused_w(const float* __restrict__ W,
                                         int cls, int co, int k) {
    int tap = k >> 9, ci = k & 511;
    int ph = cls >> 1, pw = cls & 1;
    int dh = tap >> 1, dw = tap & 1;
    int kh = ph ? (2 - 2 * dh) : (1 + 2 * dh);
    int kw = pw ? (2 - 2 * dw) : (1 + 2 * dw);
    int j = ci >> 6, u = ci & 63;
    int i = co >> 5, v = co & 31;
    int c = comp_tab[i][j];
    int wi = c < 0 ? -c : c;
    float s = c < 0 ? -1.0f : 1.0f;
    return s * W[(((wi * 64 + u) * 32 + v) * 4 + kh) * 4 + kw];
}

// Build A in fragment-major order (+ fused bias in block 0).
// m16n8k16 A fragment: reg r of lane l holds
//   row = m16*16 + (l>>2) + (r&1)*8,  cols = k16*16 + (l&3)*2 + (r>>1)*8, +1
__global__ void build_Af(const float* __restrict__ W,
                         const float* __restrict__ b) {
    int idx = blockIdx.x * 256 + threadIdx.x;
    if (blockIdx.x == 0 && threadIdx.x < COUT) {
        int t = threadIdx.x;
        int i = t >> 5, v = t & 31;
        float acc = 0.0f;
        #pragma unroll
        for (int j = 0; j < 8; j++) {
            int c = comp_tab[i][j];
            int wi = c < 0 ? -c : c;
            acc += (c < 0 ? -1.0f : 1.0f) * b[wi * 32 + v];
        }
        g_bias[t] = acc;
    }
    if (idx >= 4 * 16 * 128 * 32 * 4) return;
    int reg  = idx & 3;
    int lane = (idx >> 2) & 31;
    int k16  = (idx >> 7) & 127;
    int m16  = (idx >> 14) & 15;
    int cls  = idx >> 18;
    int co = m16 * 16 + (lane >> 2) + (reg & 1) * 8;
    int k  = k16 * 16 + (lane & 3) * 2 + (reg >> 1) * 8;
    __half h0 = __float2half(fused_w(W, cls, co, k));
    __half h1 = __float2half(fused_w(W, cls, co, k + 1));
    uint32_t v = (uint32_t)__half_as_ushort(h0)
               | ((uint32_t)__half_as_ushort(h1) << 16);
    g_Af[idx] = v;
}

// Zero the padded borders of g_Xt (rewritten every launch; deterministic)
__global__ void x_border() {
    int idx = blockIdx.x * 256 + threadIdx.x;     // over 8*66*66*64 uint4 chunks
    if (idx >= 8 * XT_HW * XT_HW * (CIN / 8)) return;
    int chunk = idx & 63;
    int cell  = idx >> 6;
    int iwp = cell % XT_HW;
    int ihp = (cell / XT_HW) % XT_HW;
    if (ihp == 0 || ihp == 65 || iwp == 0 || iwp == 65) {
        uint4 z = make_uint4(0, 0, 0, 0);
        *reinterpret_cast<uint4*>(g_Xt + (size_t)cell * CIN + chunk * 8) = z;
    }
}

// Transpose + fp16 convert: g_Xt[img][ih+1][iw+1][ci] = x[img][ci][ih][iw]
// Vectorized: float4 global reads (4 iters), uint4 fp16 writes (2 iters).
__global__ void x_transpose(const float* __restrict__ x) {
    __shared__ float t[64][65];
    int cb = blockIdx.x, ihh = blockIdx.y, img = blockIdx.z;
    int ci0 = cb * 64;
    const float* xb = x + ((size_t)(img * CIN + ci0) * HIN + ihh) * HIN;
    #pragma unroll
    for (int i = 0; i < 4; i++) {
        int e = threadIdx.x + i * 256;        // 0..1023 float4 slots
        int c = e >> 4, w4 = (e & 15) * 4;
        float4 v = *reinterpret_cast<const float4*>(xb + (size_t)c * 4096 + w4);
        t[c][w4 + 0] = v.x; t[c][w4 + 1] = v.y;
        t[c][w4 + 2] = v.z; t[c][w4 + 3] = v.w;
    }
    __syncthreads();
    __half* ob = g_Xt + ((size_t)(img * XT_HW + ihh + 1) * XT_HW + 1) * CIN + ci0;
    #pragma unroll
    for (int i = 0; i < 2; i++) {
        int e = threadIdx.x + i * 256;        // 0..511 uint4 slots
        int iw = e >> 3, c8 = (e & 7) * 8;
        __half h[8];
        #pragma unroll
        for (int u = 0; u < 8; u++) h[u] = __float2half(t[c8 + u][iw]);
        *reinterpret_cast<uint4*>(ob + (size_t)iw * CIN + c8)
            = *reinterpret_cast<uint4*>(h);
    }
}

// ------------------------------- main GEMM (HMMA) --------------------------
// grid (ntile=256, mblk=2, cls=4); block 256 (8 warps, 2x4).
// Warp tile 64(M) x 32(N). A+B staged via 3-stage cp.async; A fragments
// ping-ponged (loads one ks ahead), B fragments JIT with both LDSMs hoisted.
__global__ void __launch_bounds__(THREADS, 2) gemm_hmma(float* __restrict__ out) {
    extern __shared__ __align__(1024) char smem[];
    const uint32_t sbase = smem_u32(smem);

    const int tid  = threadIdx.x;
    const int wid  = tid >> 5;
    const int lane = tid & 31;
    const int warp_m = wid >> 2;              // 0..1 -> m offset 0/64
    const int warp_n = wid & 3;               // 0..3 -> n offset 0/32/64/96

    const int ntile = blockIdx.x;             // 0..255
    const int mblk  = blockIdx.y;             // 0..1
    const int cls   = blockIdx.z;             // 0..3
    const int ph = cls >> 1, pw = cls & 1;
    const int sgnh = ph ? 1 : -1;
    const int sgnw = pw ? 1 : -1;
    const int img  = ntile >> 5;              // 32 ntiles per image
    const int a0   = (ntile & 31) * 2;        // 2 'a' rows per tile

    // Global A fragment chunk base for this CTA (16B chunks):
    const uint32_t* __restrict__ Afg = g_Af
        + ((size_t)(cls * 16 + mblk * 8) * 128) * 32 * 4;

    float acc[4][4][4] = {};                  // [mt][nt][frag]

    // Loader: A 4 + B 4 cp.async(16B) per thread per k-tile
    auto load_tile = [&](int t) {
        const int k0  = t * BK;
        const int tap = k0 >> 9;
        const int ci0 = k0 & 511;
        const int dh = tap >> 1, dw = tap & 1;
        const int iho = sgnh * dh + 1;        // 0..2 in padded coords
        const int iwo = sgnw * dw + 1;
        const uint32_t sA = sbase + (t % STAGES) * STAGE_BYTES;
        const uint32_t sB = sA + A_TILE_BYTES;
        // A: 1024 chunks: c = (ks*8 + m16)*32 + lane  (.ca: shared with
        // the co-resident CTA -> L1 hit for the second reader)
        #pragma unroll
        for (int i = 0; i < 4; i++) {
            int c = tid + i * 256;
            int ln  = c & 31;
            int m16 = (c >> 5) & 7;
            int ks  = c >> 8;
            const uint32_t* g = Afg + ((size_t)(m16 * 128 + t * 4 + ks) * 32 + ln) * 4;
            CP_ASYNC16_CA(sA + c * 16, g);
        }
        // B: 128 rows x 8 chunks
        #pragma unroll
        for (int i = 0; i < 4; i++) {
            int c = tid + i * 256;
            int n = c >> 3, ch = c & 7;
            int b = n & 63;
            int a = a0 + (n >> 6);
            const __half* g = g_Xt
                + ((size_t)(img * XT_HW + a + iho) * XT_HW + b + iwo) * CIN
                + ci0 + ch * 8;
            CP_ASYNC16(sB + SWZ128(n * 128 + ch * 16), g);
        }
        CP_COMMIT();
    };

    // A fragment read from smem stage: conflict-free LDS.128
    auto ldA = [&](uint4* dst, uint32_t sA, int ks) {
        #pragma unroll
        for (int mt = 0; mt < 4; mt++) {
            uint32_t addr = sA + (((ks * 8 + warp_m * 4 + mt) * 32) + lane) * 16;
            LDS128(dst[mt], addr);
        }
    };

    load_tile(0);
    load_tile(1);

    // B ldmatrix.x4 lane addressing: two n-tiles per instruction.
    //   groups 0/1 -> rows ntp*16 + (lane&7), chunks kLo/kHi  -> b0,b1
    //   groups 2/3 -> rows ntp*16+8 + (lane&7), chunks kLo/kHi -> b2,b3
    const int b_row_off = warp_n * 32 + (lane & 7) + ((lane >> 4) & 1) * 8;
    const int b_ch_off  = (lane >> 3) & 1;

    uint4 a[2][4];

    #pragma unroll 1
    for (int t = 0; t < KT; t++) {
        if (t < KT - 1) { CP_WAIT1(); } else { CP_WAIT0(); }
        __syncthreads();                      // tile t ready; old reads done
        if (t + 2 < KT) load_tile(t + 2);

        const uint32_t sA = sbase + (t % STAGES) * STAGE_BYTES;
        const uint32_t sB = sA + A_TILE_BYTES;

        ldA(a[0], sA, 0);

        #pragma unroll
        for (int ks = 0; ks < 4; ks++) {
            const int cur = ks & 1, nxt = cur ^ 1;
            if (ks < 3) ldA(a[nxt], sA, ks + 1);

            // Hoist BOTH B ldmatrix issues ahead of the MMA block:
            // the second LDSM's latency is covered by the first 8 MMAs.
            uint32_t b0, b1, b2, b3, b4, b5, b6, b7;
            LDSM_X4(b0, b1, b2, b3,
                    sB + SWZ128(b_row_off * 128 + (ks * 2 + b_ch_off) * 16));
            LDSM_X4(b4, b5, b6, b7,
                    sB + SWZ128((b_row_off + 16) * 128 + (ks * 2 + b_ch_off) * 16));

            #pragma unroll
            for (int mt = 0; mt < 4; mt++) {
                MMA16816(acc[mt][0],
                         a[cur][mt].x, a[cur][mt].y, a[cur][mt].z, a[cur][mt].w,
                         b0, b1);
                MMA16816(acc[mt][1],
                         a[cur][mt].x, a[cur][mt].y, a[cur][mt].z, a[cur][mt].w,
                         b2, b3);
            }
            #pragma unroll
            for (int mt = 0; mt < 4; mt++) {
                MMA16816(acc[mt][2],
                         a[cur][mt].x, a[cur][mt].y, a[cur][mt].z, a[cur][mt].w,
                         b4, b5);
                MMA16816(acc[mt][3],
                         a[cur][mt].x, a[cur][mt].y, a[cur][mt].z, a[cur][mt].w,
                         b6, b7);
            }
        }
    }

    // ---- epilogue: fragment c layout (r,n)(r,n+1)(r+8,n)(r+8,n+1)
    #pragma unroll
    for (int mt = 0; mt < 4; mt++) {
        int co = mblk * BM + warp_m * 64 + mt * 16 + (lane >> 2);
        float bias0 = g_bias[co];
        float bias1 = g_bias[co + 8];
        float* ob0 = out + (((size_t)(img * COUT + co) * HOUT + ph) * HOUT + pw);
        float* ob1 = out + (((size_t)(img * COUT + co + 8) * HOUT + ph) * HOUT + pw);
        #pragma unroll
        for (int nt = 0; nt < 4; nt++) {
            int nl = warp_n * 32 + nt * 8 + (lane & 3) * 2;
            #pragma unroll
            for (int j = 0; j < 2; j++) {
                int n = nl + j;
                int aa = a0 + (n >> 6);
                int bb = n & 63;
                size_t off = (size_t)(aa * 2) * HOUT + bb * 2; // oh=2a+ph, ow=2b+pw in base
                ob0[off] = acc[mt][nt][j]     + bias0;
                ob1[off] = acc[mt][nt][j + 2] + bias1;
            }
        }
    }
}

// ------------------------------- launch ------------------------------------
extern "C" void kernel_launch(void* const* d_in, const int* in_sizes, int n_in,
                              void* d_out, int out_size) {
    const float* x = (const float*)d_in[0];   // [8,512,64,64]
    const float* W = (const float*)d_in[1];   // [8,64,32,4,4]
    const float* b = (const float*)d_in[2];   // [8,32]
    float* out = (float*)d_out;               // [8,256,128,128]
    (void)in_sizes; (void)n_in; (void)out_size;

    cudaFuncSetAttribute(gemm_hmma, cudaFuncAttributeMaxDynamicSharedMemorySize,
                         SMEM_BYTES);

    // 4 launches; gemm_hmma is 4th (the ncu capture slot).
    build_Af<<<(4 * 16 * 128 * 32 * 4 + 255) / 256, 256>>>(W, b);
    x_border<<<(8 * XT_HW * XT_HW * (CIN / 8) + 255) / 256, 256>>>();
    dim3 tg(8, 64, 8);
    x_transpose<<<tg, 256>>>(x);

    dim3 gg(256, 2, 4);
    gemm_hmma<<<gg, THREADS, SMEM_BYTES>>>(out);
}

// round 16
// speedup vs baseline: 1.0936x; 1.0936x over previous
#include <cuda_runtime.h>
#include <cuda_fp16.h>
#include <cstdint>

// ---------------------------------------------------------------------------
// Fused hypercomplex (8-component Cayley-Dickson) ConvTranspose2d
//   x[8,512,64,64] fp32, W[8,64,32,4,4], b[8,32] -> out[8,256,128,128]
//   4 output parity classes, each: C[256, 32768] = A[256, 2048] * B[2048, 32768]
// HMMA m16n8k16, fp16 operands, fp32 accumulation.
// Round 16: R14 GEMM exactly (.cg for BOTH operands -- .ca regressed by
//           loading the L1TEX bottleneck) + vectorized x_transpose kept.
// ---------------------------------------------------------------------------

#define CIN   512
#define COUT  256
#define HIN   64
#define HOUT  128
#define GK    2048
#define BM    128
#define BN    128
#define BK    64
#define KT    (GK / BK)       // 32 k-tiles
#define THREADS 256
#define STAGES 3

#define A_TILE_BYTES 16384                    // 4 ks x 8 m16 x 32 lane x 16 B
#define B_TILE_BYTES 16384                    // 128 rows x 128 B
#define STAGE_BYTES  (A_TILE_BYTES + B_TILE_BYTES)
#define SMEM_BYTES   (STAGES * STAGE_BYTES)   // 96 KB

// Padded transposed x: [img][ih+1:0..65][iw+1:0..65][ci] fp16, zero borders
#define XT_HW 66
__device__ __align__(1024) __half g_Xt[8 * XT_HW * XT_HW * CIN];  // ~34 MB
// A in m16n8k16 fragment-major order:
// [cls 4][m16 16][k16 128][lane 32][reg 4] as uint32 (reg = pair of halves)
__device__ __align__(1024) uint32_t g_Af[4 * 16 * 128 * 32 * 4];  // 4 MB
__device__ __align__(16)   float  g_bias[COUT];

// Cayley-Dickson component table for n=8 (validated in round 1)
__device__ const int comp_tab[8][8] = {
    { 0,-1,-2,-1,-4,-3,-2,-3},
    { 1, 0,-3,-2,-5,-4,-1,-2},
    { 2, 1, 0,-1,-6,-5,-4,-3},
    { 3, 2, 1, 0,-7,-6,-5,-4},
    { 4, 3, 2, 3, 0,-1,-2,-1},
    { 5, 4, 1, 2, 1, 0,-3,-2},
    { 6, 5, 4, 3, 2, 1, 0,-1},
    { 7, 6, 5, 4, 3, 2, 1, 0},
};

// ------------------------------- PTX helpers -------------------------------
__device__ __forceinline__ uint32_t smem_u32(const void* p) {
    return (uint32_t)__cvta_generic_to_shared(p);
}

#define SWZ128(o) ((o) ^ (((o) >> 3) & 0x70))

#define CP_ASYNC16(smem_addr, gptr) \
    asm volatile("cp.async.cg.shared.global [%0], [%1], 16;" \
                 :: "r"(smem_addr), "l"(gptr) : "memory")
#define CP_COMMIT() asm volatile("cp.async.commit_group;" ::: "memory")
#define CP_WAIT0()  asm volatile("cp.async.wait_group 0;" ::: "memory")
#define CP_WAIT1()  asm volatile("cp.async.wait_group 1;" ::: "memory")

#define LDSM_X4(r0, r1, r2, r3, addr) \
    asm volatile("ldmatrix.sync.aligned.m8n8.x4.shared.b16 {%0,%1,%2,%3}, [%4];" \
                 : "=r"(r0), "=r"(r1), "=r"(r2), "=r"(r3) : "r"(addr))

#define LDS128(v, addr) \
    asm volatile("ld.shared.v4.u32 {%0,%1,%2,%3}, [%4];" \
                 : "=r"((v).x), "=r"((v).y), "=r"((v).z), "=r"((v).w) \
                 : "r"(addr))

#define MMA16816(d, a0, a1, a2, a3, b0, b1) \
    asm volatile("mma.sync.aligned.m16n8k16.row.col.f32.f16.f16.f32 " \
                 "{%0,%1,%2,%3}, {%4,%5,%6,%7}, {%8,%9}, {%0,%1,%2,%3};" \
                 : "+f"((d)[0]), "+f"((d)[1]), "+f"((d)[2]), "+f"((d)[3]) \
                 : "r"(a0), "r"(a1), "r"(a2), "r"(a3), "r"(b0), "r"(b1))

// ------------------------------- prep kernels ------------------------------

// Fused weight value for (cls, co, k) where k = tap*512 + ci
__device__ __forceinline__ float fused_w(const float* __restrict__ W,
                                         int cls, int co, int k) {
    int tap = k >> 9, ci = k & 511;
    int ph = cls >> 1, pw = cls & 1;
    int dh = tap >> 1, dw = tap & 1;
    int kh = ph ? (2 - 2 * dh) : (1 + 2 * dh);
    int kw = pw ? (2 - 2 * dw) : (1 + 2 * dw);
    int j = ci >> 6, u = ci & 63;
    int i = co >> 5, v = co & 31;
    int c = comp_tab[i][j];
    int wi = c < 0 ? -c : c;
    float s = c < 0 ? -1.0f : 1.0f;
    return s * W[(((wi * 64 + u) * 32 + v) * 4 + kh) * 4 + kw];
}

// Build A in fragment-major order (+ fused bias in block 0).
// m16n8k16 A fragment: reg r of lane l holds
//   row = m16*16 + (l>>2) + (r&1)*8,  cols = k16*16 + (l&3)*2 + (r>>1)*8, +1
__global__ void build_Af(const float* __restrict__ W,
                         const float* __restrict__ b) {
    int idx = blockIdx.x * 256 + threadIdx.x;
    if (blockIdx.x == 0 && threadIdx.x < COUT) {
        int t = threadIdx.x;
        int i = t >> 5, v = t & 31;
        float acc = 0.0f;
        #pragma unroll
        for (int j = 0; j < 8; j++) {
            int c = comp_tab[i][j];
            int wi = c < 0 ? -c : c;
            acc += (c < 0 ? -1.0f : 1.0f) * b[wi * 32 + v];
        }
        g_bias[t] = acc;
    }
    if (idx >= 4 * 16 * 128 * 32 * 4) return;
    int reg  = idx & 3;
    int lane = (idx >> 2) & 31;
    int k16  = (idx >> 7) & 127;
    int m16  = (idx >> 14) & 15;
    int cls  = idx >> 18;
    int co = m16 * 16 + (lane >> 2) + (reg & 1) * 8;
    int k  = k16 * 16 + (lane & 3) * 2 + (reg >> 1) * 8;
    __half h0 = __float2half(fused_w(W, cls, co, k));
    __half h1 = __float2half(fused_w(W, cls, co, k + 1));
    uint32_t v = (uint32_t)__half_as_ushort(h0)
               | ((uint32_t)__half_as_ushort(h1) << 16);
    g_Af[idx] = v;
}

// Zero the padded borders of g_Xt (rewritten every launch; deterministic)
__global__ void x_border() {
    int idx = blockIdx.x * 256 + threadIdx.x;     // over 8*66*66*64 uint4 chunks
    if (idx >= 8 * XT_HW * XT_HW * (CIN / 8)) return;
    int chunk = idx & 63;
    int cell  = idx >> 6;
    int iwp = cell % XT_HW;
    int ihp = (cell / XT_HW) % XT_HW;
    if (ihp == 0 || ihp == 65 || iwp == 0 || iwp == 65) {
        uint4 z = make_uint4(0, 0, 0, 0);
        *reinterpret_cast<uint4*>(g_Xt + (size_t)cell * CIN + chunk * 8) = z;
    }
}

// Transpose + fp16 convert: g_Xt[img][ih+1][iw+1][ci] = x[img][ci][ih][iw]
// Vectorized: float4 global reads (4 iters), uint4 fp16 writes (2 iters).
__global__ void x_transpose(const float* __restrict__ x) {
    __shared__ float t[64][65];
    int cb = blockIdx.x, ihh = blockIdx.y, img = blockIdx.z;
    int ci0 = cb * 64;
    const float* xb = x + ((size_t)(img * CIN + ci0) * HIN + ihh) * HIN;
    #pragma unroll
    for (int i = 0; i < 4; i++) {
        int e = threadIdx.x + i * 256;        // 0..1023 float4 slots
        int c = e >> 4, w4 = (e & 15) * 4;
        float4 v = *reinterpret_cast<const float4*>(xb + (size_t)c * 4096 + w4);
        t[c][w4 + 0] = v.x; t[c][w4 + 1] = v.y;
        t[c][w4 + 2] = v.z; t[c][w4 + 3] = v.w;
    }
    __syncthreads();
    __half* ob = g_Xt + ((size_t)(img * XT_HW + ihh + 1) * XT_HW + 1) * CIN + ci0;
    #pragma unroll
    for (int i = 0; i < 2; i++) {
        int e = threadIdx.x + i * 256;        // 0..511 uint4 slots
        int iw = e >> 3, c8 = (e & 7) * 8;
        __half h[8];
        #pragma unroll
        for (int u = 0; u < 8; u++) h[u] = __float2half(t[c8 + u][iw]);
        *reinterpret_cast<uint4*>(ob + (size_t)iw * CIN + c8)
            = *reinterpret_cast<uint4*>(h);
    }
}

// ------------------------------- main GEMM (HMMA) --------------------------
// grid (ntile=256, mblk=2, cls=4); block 256 (8 warps, 2x4).
// Warp tile 64(M) x 32(N). A+B staged via 3-stage cp.async (.cg); A fragments
// ping-ponged (loads one ks ahead), B fragments JIT with both LDSMs hoisted.
__global__ void __launch_bounds__(THREADS, 2) gemm_hmma(float* __restrict__ out) {
    extern __shared__ __align__(1024) char smem[];
    const uint32_t sbase = smem_u32(smem);

    const int tid  = threadIdx.x;
    const int wid  = tid >> 5;
    const int lane = tid & 31;
    const int warp_m = wid >> 2;              // 0..1 -> m offset 0/64
    const int warp_n = wid & 3;               // 0..3 -> n offset 0/32/64/96

    const int ntile = blockIdx.x;             // 0..255
    const int mblk  = blockIdx.y;             // 0..1
    const int cls   = blockIdx.z;             // 0..3
    const int ph = cls >> 1, pw = cls & 1;
    const int sgnh = ph ? 1 : -1;
    const int sgnw = pw ? 1 : -1;
    const int img  = ntile >> 5;              // 32 ntiles per image
    const int a0   = (ntile & 31) * 2;        // 2 'a' rows per tile

    // Global A fragment chunk base for this CTA (16B chunks):
    const uint32_t* __restrict__ Afg = g_Af
        + ((size_t)(cls * 16 + mblk * 8) * 128) * 32 * 4;

    float acc[4][4][4] = {};                  // [mt][nt][frag]

    // Loader: A 4 + B 4 cp.async(16B) per thread per k-tile
    auto load_tile = [&](int t) {
        const int k0  = t * BK;
        const int tap = k0 >> 9;
        const int ci0 = k0 & 511;
        const int dh = tap >> 1, dw = tap & 1;
        const int iho = sgnh * dh + 1;        // 0..2 in padded coords
        const int iwo = sgnw * dw + 1;
        const uint32_t sA = sbase + (t % STAGES) * STAGE_BYTES;
        const uint32_t sB = sA + A_TILE_BYTES;
        // A: 1024 chunks: c = (ks*8 + m16)*32 + lane
        #pragma unroll
        for (int i = 0; i < 4; i++) {
            int c = tid + i * 256;
            int ln  = c & 31;
            int m16 = (c >> 5) & 7;
            int ks  = c >> 8;
            const uint32_t* g = Afg + ((size_t)(m16 * 128 + t * 4 + ks) * 32 + ln) * 4;
            CP_ASYNC16(sA + c * 16, g);
        }
        // B: 128 rows x 8 chunks
        #pragma unroll
        for (int i = 0; i < 4; i++) {
            int c = tid + i * 256;
            int n = c >> 3, ch = c & 7;
            int b = n & 63;
            int a = a0 + (n >> 6);
            const __half* g = g_Xt
                + ((size_t)(img * XT_HW + a + iho) * XT_HW + b + iwo) * CIN
                + ci0 + ch * 8;
            CP_ASYNC16(sB + SWZ128(n * 128 + ch * 16), g);
        }
        CP_COMMIT();
    };

    // A fragment read from smem stage: conflict-free LDS.128
    auto ldA = [&](uint4* dst, uint32_t sA, int ks) {
        #pragma unroll
        for (int mt = 0; mt < 4; mt++) {
            uint32_t addr = sA + (((ks * 8 + warp_m * 4 + mt) * 32) + lane) * 16;
            LDS128(dst[mt], addr);
        }
    };

    load_tile(0);
    load_tile(1);

    // B ldmatrix.x4 lane addressing: two n-tiles per instruction.
    //   groups 0/1 -> rows ntp*16 + (lane&7), chunks kLo/kHi  -> b0,b1
    //   groups 2/3 -> rows ntp*16+8 + (lane&7), chunks kLo/kHi -> b2,b3
    const int b_row_off = warp_n * 32 + (lane & 7) + ((lane >> 4) & 1) * 8;
    const int b_ch_off  = (lane >> 3) & 1;

    uint4 a[2][4];

    #pragma unroll 1
    for (int t = 0; t < KT; t++) {
        if (t < KT - 1) { CP_WAIT1(); } else { CP_WAIT0(); }
        __syncthreads();                      // tile t ready; old reads done
        if (t + 2 < KT) load_tile(t + 2);

        const uint32_t sA = sbase + (t % STAGES) * STAGE_BYTES;
        const uint32_t sB = sA + A_TILE_BYTES;

        ldA(a[0], sA, 0);

        #pragma unroll
        for (int ks = 0; ks < 4; ks++) {
            const int cur = ks & 1, nxt = cur ^ 1;
            if (ks < 3) ldA(a[nxt], sA, ks + 1);

            // Hoist BOTH B ldmatrix issues ahead of the MMA block:
            // the second LDSM's latency is covered by the first 8 MMAs.
            uint32_t b0, b1, b2, b3, b4, b5, b6, b7;
            LDSM_X4(b0, b1, b2, b3,
                    sB + SWZ128(b_row_off * 128 + (ks * 2 + b_ch_off) * 16));
            LDSM_X4(b4, b5, b6, b7,
                    sB + SWZ128((b_row_off + 16) * 128 + (ks * 2 + b_ch_off) * 16));

            #pragma unroll
            for (int mt = 0; mt < 4; mt++) {
                MMA16816(acc[mt][0],
                         a[cur][mt].x, a[cur][mt].y, a[cur][mt].z, a[cur][mt].w,
                         b0, b1);
                MMA16816(acc[mt][1],
                         a[cur][mt].x, a[cur][mt].y, a[cur][mt].z, a[cur][mt].w,
                         b2, b3);
            }
            #pragma unroll
            for (int mt = 0; mt < 4; mt++) {
                MMA16816(acc[mt][2],
                         a[cur][mt].x, a[cur][mt].y, a[cur][mt].z, a[cur][mt].w,
                         b4, b5);
                MMA16816(acc[mt][3],
                         a[cur][mt].x, a[cur][mt].y, a[cur][mt].z, a[cur][mt].w,
                         b6, b7);
            }
        }
    }

    // ---- epilogue: fragment c layout (r,n)(r,n+1)(r+8,n)(r+8,n+1)
    #pragma unroll
    for (int mt = 0; mt < 4; mt++) {
        int co = mblk * BM + warp_m * 64 + mt * 16 + (lane >> 2);
        float bias0 = g_bias[co];
        float bias1 = g_bias[co + 8];
        float* ob0 = out + (((size_t)(img * COUT + co) * HOUT + ph) * HOUT + pw);
        float* ob1 = out + (((size_t)(img * COUT + co + 8) * HOUT + ph) * HOUT + pw);
        #pragma unroll
        for (int nt = 0; nt < 4; nt++) {
            int nl = warp_n * 32 + nt * 8 + (lane & 3) * 2;
            #pragma unroll
            for (int j = 0; j < 2; j++) {
                int n = nl + j;
                int aa = a0 + (n >> 6);
                int bb = n & 63;
                size_t off = (size_t)(aa * 2) * HOUT + bb * 2; // oh=2a+ph, ow=2b+pw in base
                ob0[off] = acc[mt][nt][j]     + bias0;
                ob1[off] = acc[mt][nt][j + 2] + bias1;
            }
        }
    }
}

// ------------------------------- launch ------------------------------------
extern "C" void kernel_launch(void* const* d_in, const int* in_sizes, int n_in,
                              void* d_out, int out_size) {
    const float* x = (const float*)d_in[0];   // [8,512,64,64]
    const float* W = (const float*)d_in[1];   // [8,64,32,4,4]
    const float* b = (const float*)d_in[2];   // [8,32]
    float* out = (float*)d_out;               // [8,256,128,128]
    (void)in_sizes; (void)n_in; (void)out_size;

    cudaFuncSetAttribute(gemm_hmma, cudaFuncAttributeMaxDynamicSharedMemorySize,
                         SMEM_BYTES);

    // 4 launches; gemm_hmma is 4th (the ncu capture slot).
    build_Af<<<(4 * 16 * 128 * 32 * 4 + 255) / 256, 256>>>(W, b);
    x_border<<<(8 * XT_HW * XT_HW * (CIN / 8) + 255) / 256, 256>>>();
    dim3 tg(8, 64, 8);
    x_transpose<<<tg, 256>>>(x);

    dim3 gg(256, 2, 4);
    gemm_hmma<<<gg, THREADS, SMEM_BYTES>>>(out);
}